// round 14
// baseline (speedup 1.0000x reference)
#include <cuda_runtime.h>

// ROIAlign / crop_and_resize (bilinear, extrapolation_value = 0)
// feature_map: [8, 64, 64, 256] f32 (B,H,W,C), rois: [8,128,4] f32
// out: [1024, 14, 14, 256] f32
//
// Best-known structure (R12/R13): one warp per output pixel; 128-thread
// blocks; __launch_bounds__(128,16) caps regs at 32 => full 64 warps/SM;
// 8 independent gather LDG.128 (L1::evict_last) issued before any consume;
// 32-bit byte addressing. This round: DEFAULT write-back stores (no .cs) so
// L2 accumulates full lines and coalesces the 205MB write stream's
// writebacks instead of evicting early.

#define B 8
#define H 64
#define W 64
#define C 256
#define NUM_ROIS 128
#define CROP 14
#define PIX_PER_ROI (CROP * CROP)               // 196
#define TOTAL_PIX (B * NUM_ROIS * PIX_PER_ROI)  // 200704
#define WARPS_PER_BLOCK 4

__device__ __forceinline__ float4 ldg_evict_last(const void* p)
{
    float4 v;
    asm("ld.global.nc.L1::evict_last.v4.f32 {%0,%1,%2,%3}, [%4];"
        : "=f"(v.x), "=f"(v.y), "=f"(v.z), "=f"(v.w)
        : "l"(p));
    return v;
}

__global__ __launch_bounds__(128, 16) void roialign_kernel(
    const float* __restrict__ fm,
    const float* __restrict__ rois,
    float* __restrict__ out)
{
    const int lane = threadIdx.x & 31;
    const int wid  = threadIdx.x >> 5;
    const int pix  = blockIdx.x * WARPS_PER_BLOCK + wid;   // grid divides exactly

    // Decompose pixel id (warp-uniform)
    const int n   = pix / PIX_PER_ROI;
    const int rem = pix - n * PIX_PER_ROI;
    const int i   = rem / CROP;
    const int j   = rem - i * CROP;
    const int b   = n >> 7;

    // ROI coords: warp-broadcast 16B load
    const float4 r = __ldg((const float4*)(rois + n * 4));
    const float y1 = r.x, x1 = r.y, y2 = r.z, x2 = r.w;

    const float h_scale = (y2 - y1) * (float)(H - 1) / (float)(CROP - 1);
    const float w_scale = (x2 - x1) * (float)(W - 1) / (float)(CROP - 1);
    const float in_y = fmaf((float)i, h_scale, y1 * (float)(H - 1));
    const float in_x = fmaf((float)j, w_scale, x1 * (float)(W - 1));

    const bool valid = (in_y >= 0.f) && (in_y <= (float)(H - 1)) &&
                       (in_x >= 0.f) && (in_x <= (float)(W - 1));

    const float fy = floorf(in_y);
    const float fx = floorf(in_x);
    const float yl = in_y - fy;
    const float xl = in_x - fx;

    int ty = min(max((int)fy, 0), H - 1);
    int by = min(max((int)ceilf(in_y), 0), H - 1);
    int lx = min(max((int)fx, 0), W - 1);
    int rx = min(max((int)ceilf(in_x), 0), W - 1);

    // Bilinear weights; zeroed when invalid (output becomes exact 0)
    float wtl = (1.f - xl) * (1.f - yl);
    float wtr = xl * (1.f - yl);
    float wbl = (1.f - xl) * yl;
    float wbr = xl * yl;
    if (!valid) { wtl = wtr = wbl = wbr = 0.f; ty = by = lx = rx = 0; }

    // 32-bit byte offsets: fm is 33.5MB, out is 205MB — both fit in int
    const char* fmb = (const char*)fm;
    const int cb   = lane * 16;
    const int base = b * (H * W * C * 4);
    const int oT   = base + ty * (W * C * 4) + cb;
    const int oB   = base + by * (W * C * 4) + cb;
    const int oL   = lx * (C * 4);
    const int oR   = rx * (C * 4);

    // 8 independent gathers (two 128-channel halves), all issued up front
    const float4 tl0 = ldg_evict_last(fmb + oT + oL);
    const float4 tr0 = ldg_evict_last(fmb + oT + oR);
    const float4 bl0 = ldg_evict_last(fmb + oB + oL);
    const float4 br0 = ldg_evict_last(fmb + oB + oR);
    const float4 tl1 = ldg_evict_last(fmb + oT + oL + 512);
    const float4 tr1 = ldg_evict_last(fmb + oT + oR + 512);
    const float4 bl1 = ldg_evict_last(fmb + oB + oL + 512);
    const float4 br1 = ldg_evict_last(fmb + oB + oR + 512);

    char* ob = (char*)out + pix * (C * 4) + cb;

    float4 o0;
    o0.x = fmaf(tl0.x, wtl, fmaf(tr0.x, wtr, fmaf(bl0.x, wbl, br0.x * wbr)));
    o0.y = fmaf(tl0.y, wtl, fmaf(tr0.y, wtr, fmaf(bl0.y, wbl, br0.y * wbr)));
    o0.z = fmaf(tl0.z, wtl, fmaf(tr0.z, wtr, fmaf(bl0.z, wbl, br0.z * wbr)));
    o0.w = fmaf(tl0.w, wtl, fmaf(tr0.w, wtr, fmaf(bl0.w, wbl, br0.w * wbr)));
    *(float4*)ob = o0;            // default write-back store

    float4 o1;
    o1.x = fmaf(tl1.x, wtl, fmaf(tr1.x, wtr, fmaf(bl1.x, wbl, br1.x * wbr)));
    o1.y = fmaf(tl1.y, wtl, fmaf(tr1.y, wtr, fmaf(bl1.y, wbl, br1.y * wbr)));
    o1.z = fmaf(tl1.z, wtl, fmaf(tr1.z, wtr, fmaf(bl1.z, wbl, br1.z * wbr)));
    o1.w = fmaf(tl1.w, wtl, fmaf(tr1.w, wtr, fmaf(bl1.w, wbl, br1.w * wbr)));
    *(float4*)(ob + 512) = o1;    // default write-back store
}

extern "C" void kernel_launch(void* const* d_in, const int* in_sizes, int n_in,
                              void* d_out, int out_size)
{
    const float* fm   = (const float*)d_in[0];
    const float* rois = (const float*)d_in[1];
    float* out = (float*)d_out;

    roialign_kernel<<<TOTAL_PIX / WARPS_PER_BLOCK, 128>>>(fm, rois, out);
}

// round 15
// speedup vs baseline: 1.0917x; 1.0917x over previous
#include <cuda_runtime.h>

// ROIAlign / crop_and_resize (bilinear, extrapolation_value = 0)  — FINAL
// feature_map: [8, 64, 64, 256] f32 (B,H,W,C), rois: [8,128,4] f32
// out: [1024, 14, 14, 256] f32
//
// Converged configuration (69.6us -> 49.3us over 13 rounds):
//  - one warp per output pixel; lane covers channels [lane*4,+4) and
//    [128+lane*4,+4): 8 independent gather LDG.128 issued before any consume
//  - 128-thread blocks (scan: 64/128/256 -> 128 best)
//  - __launch_bounds__(128,16): regs capped at 32 => full 64 warps/SM
//  - gathers: ld.global.nc.L1::evict_last (fm reused across pixel-warps)
//  - stores: __stcs evict-first (output never re-read; keeps L2 for fm,
//    smooths writeback between graph replays; .wb and .wt both measured worse)
//  - 32-bit byte addressing (fm 33.5MB, out 205MB < 2^31)

#define B 8
#define H 64
#define W 64
#define C 256
#define NUM_ROIS 128
#define CROP 14
#define PIX_PER_ROI (CROP * CROP)               // 196
#define TOTAL_PIX (B * NUM_ROIS * PIX_PER_ROI)  // 200704
#define WARPS_PER_BLOCK 4

__device__ __forceinline__ float4 ldg_evict_last(const void* p)
{
    float4 v;
    asm("ld.global.nc.L1::evict_last.v4.f32 {%0,%1,%2,%3}, [%4];"
        : "=f"(v.x), "=f"(v.y), "=f"(v.z), "=f"(v.w)
        : "l"(p));
    return v;
}

__global__ __launch_bounds__(128, 16) void roialign_kernel(
    const float* __restrict__ fm,
    const float* __restrict__ rois,
    float* __restrict__ out)
{
    const int lane = threadIdx.x & 31;
    const int wid  = threadIdx.x >> 5;
    const int pix  = blockIdx.x * WARPS_PER_BLOCK + wid;   // grid divides exactly

    // Decompose pixel id (warp-uniform)
    const int n   = pix / PIX_PER_ROI;
    const int rem = pix - n * PIX_PER_ROI;
    const int i   = rem / CROP;
    const int j   = rem - i * CROP;
    const int b   = n >> 7;

    // ROI coords: warp-broadcast 16B load
    const float4 r = __ldg((const float4*)(rois + n * 4));
    const float y1 = r.x, x1 = r.y, y2 = r.z, x2 = r.w;

    const float h_scale = (y2 - y1) * (float)(H - 1) / (float)(CROP - 1);
    const float w_scale = (x2 - x1) * (float)(W - 1) / (float)(CROP - 1);
    const float in_y = fmaf((float)i, h_scale, y1 * (float)(H - 1));
    const float in_x = fmaf((float)j, w_scale, x1 * (float)(W - 1));

    const bool valid = (in_y >= 0.f) && (in_y <= (float)(H - 1)) &&
                       (in_x >= 0.f) && (in_x <= (float)(W - 1));

    const float fy = floorf(in_y);
    const float fx = floorf(in_x);
    const float yl = in_y - fy;
    const float xl = in_x - fx;

    int ty = min(max((int)fy, 0), H - 1);
    int by = min(max((int)ceilf(in_y), 0), H - 1);
    int lx = min(max((int)fx, 0), W - 1);
    int rx = min(max((int)ceilf(in_x), 0), W - 1);

    // Bilinear weights; zeroed when invalid (output becomes exact 0)
    float wtl = (1.f - xl) * (1.f - yl);
    float wtr = xl * (1.f - yl);
    float wbl = (1.f - xl) * yl;
    float wbr = xl * yl;
    if (!valid) { wtl = wtr = wbl = wbr = 0.f; ty = by = lx = rx = 0; }

    // 32-bit byte offsets
    const char* fmb = (const char*)fm;
    const int cb   = lane * 16;
    const int base = b * (H * W * C * 4);
    const int oT   = base + ty * (W * C * 4) + cb;
    const int oB   = base + by * (W * C * 4) + cb;
    const int oL   = lx * (C * 4);
    const int oR   = rx * (C * 4);

    // 8 independent gathers (two 128-channel halves), all issued up front
    const float4 tl0 = ldg_evict_last(fmb + oT + oL);
    const float4 tr0 = ldg_evict_last(fmb + oT + oR);
    const float4 bl0 = ldg_evict_last(fmb + oB + oL);
    const float4 br0 = ldg_evict_last(fmb + oB + oR);
    const float4 tl1 = ldg_evict_last(fmb + oT + oL + 512);
    const float4 tr1 = ldg_evict_last(fmb + oT + oR + 512);
    const float4 bl1 = ldg_evict_last(fmb + oB + oL + 512);
    const float4 br1 = ldg_evict_last(fmb + oB + oR + 512);

    char* ob = (char*)out + pix * (C * 4) + cb;

    float4 o0;
    o0.x = fmaf(tl0.x, wtl, fmaf(tr0.x, wtr, fmaf(bl0.x, wbl, br0.x * wbr)));
    o0.y = fmaf(tl0.y, wtl, fmaf(tr0.y, wtr, fmaf(bl0.y, wbl, br0.y * wbr)));
    o0.z = fmaf(tl0.z, wtl, fmaf(tr0.z, wtr, fmaf(bl0.z, wbl, br0.z * wbr)));
    o0.w = fmaf(tl0.w, wtl, fmaf(tr0.w, wtr, fmaf(bl0.w, wbl, br0.w * wbr)));
    __stcs((float4*)ob, o0);

    float4 o1;
    o1.x = fmaf(tl1.x, wtl, fmaf(tr1.x, wtr, fmaf(bl1.x, wbl, br1.x * wbr)));
    o1.y = fmaf(tl1.y, wtl, fmaf(tr1.y, wtr, fmaf(bl1.y, wbl, br1.y * wbr)));
    o1.z = fmaf(tl1.z, wtl, fmaf(tr1.z, wtr, fmaf(bl1.z, wbl, br1.z * wbr)));
    o1.w = fmaf(tl1.w, wtl, fmaf(tr1.w, wtr, fmaf(bl1.w, wbl, br1.w * wbr)));
    __stcs((float4*)(ob + 512), o1);
}

extern "C" void kernel_launch(void* const* d_in, const int* in_sizes, int n_in,
                              void* d_out, int out_size)
{
    const float* fm   = (const float*)d_in[0];
    const float* rois = (const float*)d_in[1];
    float* out = (float*)d_out;

    roialign_kernel<<<TOTAL_PIX / WARPS_PER_BLOCK, 128>>>(fm, rois, out);
}